// round 5
// baseline (speedup 1.0000x reference)
#include <cuda_runtime.h>
#include <cuda_bf16.h>

// Problem constants
#define BATCH   8
#define IN_P    16     // in_planes
#define REP_C   16     // PROD_DW / IN_PLANES
#define OUT_P   32     // out_planes
#define PV      256    // 32*32 pixels / 4 (float4 pixel-vecs)
#define C_X     256    // PROD_DW channels of x
#define C_OUT1  8192   // OUT_P * PROD_DW
#define OC_N    4      // o-chunks
#define O_PER_C 8      // o per chunk

#define OUT1_VECS ((size_t)BATCH * C_OUT1 * PV)   // 16777216 float4

// Gate bitmasks: [oc][b][i][p] -> uint4 (one uint32 per pixel component,
// bit oo = gate for o = oc*8+oo).  4*8*16*256 * 16B = 2 MB scratch.
__device__ uint4 g_mask[OC_N * BATCH * IN_P * PV];

// ---------------------------------------------------------------------------
// Kernel A: compute gate bits (exact reference rounding: sequential sum of the
// PRODUCTS w*x_r over r) and the small dense relu_out2 path. Also pre-warms x
// into L2 for kernel B.
// ---------------------------------------------------------------------------
__global__ __launch_bounds__(256) void gate_kernel(
    const float4* __restrict__ x,      // (B,256,256) float4
    const float4* __restrict__ x2,     // (B,16,256)  float4
    const float*  __restrict__ w,      // (32,16)
    float4* __restrict__ out)
{
    const int blk = blockIdx.x;        // 0..511
    const int oc  = blk & 3;
    const int i   = (blk >> 2) & 15;
    const int b   = blk >> 6;
    const int p   = threadIdx.x;

    __shared__ float ws[OUT_P * IN_P];
    ws[p] = w[p];
    ws[p + 256] = w[p + 256];
    __syncthreads();

    const float4* xc = x + ((size_t)b * C_X + (size_t)i * REP_C) * PV + p;
    float4 xr[REP_C];
    #pragma unroll
    for (int r = 0; r < REP_C; r++)
        xr[r] = __ldg(&xc[(size_t)r * PV]);

    uint4 m = make_uint4(0u, 0u, 0u, 0u);
    #pragma unroll
    for (int oo = 0; oo < O_PER_C; oo++) {
        const float wv = ws[(oc * O_PER_C + oo) * IN_P + i];
        float tx = 0.f, ty = 0.f, tz = 0.f, tw = 0.f;
        #pragma unroll
        for (int r = 0; r < REP_C; r++) {
            tx += wv * xr[r].x;
            ty += wv * xr[r].y;
            tz += wv * xr[r].z;
            tw += wv * xr[r].w;
        }
        m.x |= (tx > 0.f ? 1u : 0u) << oo;
        m.y |= (ty > 0.f ? 1u : 0u) << oo;
        m.z |= (tz > 0.f ? 1u : 0u) << oo;
        m.w |= (tw > 0.f ? 1u : 0u) << oo;
    }
    g_mask[(((size_t)oc * BATCH + b) * IN_P + i) * PV + p] = m;

    // Dense 1x1 conv + ReLU (tiny): i==0 blocks do their 8 o values.
    if (i == 0) {
        const float4* x2b = x2 + (size_t)b * IN_P * PV + p;
        float ax[O_PER_C], ay[O_PER_C], az[O_PER_C], aw[O_PER_C];
        #pragma unroll
        for (int oo = 0; oo < O_PER_C; oo++)
            ax[oo] = ay[oo] = az[oo] = aw[oo] = 0.f;

        #pragma unroll
        for (int ii = 0; ii < IN_P; ii++) {   // sequential ii: match einsum
            const float4 v = __ldg(&x2b[(size_t)ii * PV]);
            #pragma unroll
            for (int oo = 0; oo < O_PER_C; oo++) {
                const float wv = ws[(oc * O_PER_C + oo) * IN_P + ii];
                ax[oo] = fmaf(wv, v.x, ax[oo]);
                ay[oo] = fmaf(wv, v.y, ay[oo]);
                az[oo] = fmaf(wv, v.z, az[oo]);
                aw[oo] = fmaf(wv, v.w, aw[oo]);
            }
        }
        #pragma unroll
        for (int oo = 0; oo < O_PER_C; oo++) {
            float4 r;
            r.x = fmaxf(ax[oo], 0.f);
            r.y = fmaxf(ay[oo], 0.f);
            r.z = fmaxf(az[oo], 0.f);
            r.w = fmaxf(aw[oo], 0.f);
            out[OUT1_VECS + ((size_t)b * OUT_P + oc * O_PER_C + oo) * PV + p] = r;
        }
    }
}

// ---------------------------------------------------------------------------
// Kernel B: pure store streamer. Only 8 x-vecs live per thread (r-half split)
// so regs fit 4 blocks/SM -> ~2.3x the warp concurrency of R3 for the same
// byte traffic. x reads are L2 hits (pre-warmed by kernel A).
// ---------------------------------------------------------------------------
__global__ __launch_bounds__(256, 4) void store_kernel(
    const float4* __restrict__ x,
    const float*  __restrict__ w,
    float4* __restrict__ out)
{
    const int blk = blockIdx.x;        // 0..1023
    const int oc  = blk & 3;           // o-chunk (8 o)
    const int rh  = (blk >> 2) & 1;    // r-half (8 r)
    const int i   = (blk >> 3) & 15;
    const int b   = blk >> 7;
    const int p   = threadIdx.x;

    __shared__ float ws[OUT_P * IN_P];
    ws[p] = w[p];
    ws[p + 256] = w[p + 256];
    __syncthreads();

    const int r0 = rh * 8;
    const float4* xc = x + ((size_t)b * C_X + (size_t)i * REP_C + r0) * PV + p;
    float4 xr[8];
    #pragma unroll
    for (int rr = 0; rr < 8; rr++)
        xr[rr] = __ldg(&xc[(size_t)rr * PV]);

    const uint4 m = g_mask[(((size_t)oc * BATCH + b) * IN_P + i) * PV + p];

    float4* ob = out + ((size_t)b * C_OUT1 + (size_t)i * REP_C + r0) * PV + p;

    #pragma unroll
    for (int oo = 0; oo < O_PER_C; oo++) {
        const int o = oc * O_PER_C + oo;
        const float wv = ws[o * IN_P + i];
        const float gx = ((m.x >> oo) & 1u) ? wv : 0.f;
        const float gy = ((m.y >> oo) & 1u) ? wv : 0.f;
        const float gz = ((m.z >> oo) & 1u) ? wv : 0.f;
        const float gw = ((m.w >> oo) & 1u) ? wv : 0.f;

        float4* dst = ob + (size_t)o * (C_X * PV);
        #pragma unroll
        for (int rr = 0; rr < 8; rr++) {
            float4 s;
            s.x = gx * xr[rr].x;
            s.y = gy * xr[rr].y;
            s.z = gz * xr[rr].z;
            s.w = gw * xr[rr].w;
            __stcs(&dst[(size_t)rr * PV], s);
        }
    }
}

extern "C" void kernel_launch(void* const* d_in, const int* in_sizes, int n_in,
                              void* d_out, int out_size)
{
    const float4* x  = (const float4*)d_in[0];
    const float4* x2 = (const float4*)d_in[1];
    const float*  w  = (const float*) d_in[2];
    float4* out = (float4*)d_out;

    gate_kernel <<<BATCH * IN_P * OC_N,     256>>>(x, x2, w, out);
    store_kernel<<<BATCH * IN_P * 2 * OC_N, 256>>>(x, w, out);
}

// round 7
// speedup vs baseline: 1.1370x; 1.1370x over previous
#include <cuda_runtime.h>
#include <cuda_bf16.h>

// Problem constants
#define BATCH   8
#define IN_P    16     // in_planes
#define REP_C   16     // PROD_DW / IN_PLANES
#define OUT_P   32     // out_planes
#define PV      256    // 32*32 pixels / 4 (float4 pixel-vecs)
#define C_X     256    // PROD_DW channels of x
#define C_OUT1  8192   // OUT_P * PROD_DW
#define O_PER_C 8      // o values per block

#define OUT1_VECS ((size_t)BATCH * C_OUT1 * PV)   // 16777216 float4

// Block = (b, i, o-chunk-of-8, pixel-half). 128 threads, each owns one
// pixel-vec: loads its 16 rep-channels of x ONCE into registers, computes all
// 8 gate bits (reference rounding: sequential sum of the PRODUCTS w*x_r), then
// streams 8x16 float4 stores. Same per-block work as the proven R3 kernel
// (tail granularity preserved) but half the x reads and 2x the stores per load.
__global__ __launch_bounds__(128) void qconv_pw_kernel(
    const float4* __restrict__ x,      // (B,256,1024) -> (B,256,256) float4
    const float4* __restrict__ x2,     // (B,16,1024)  -> (B,16,256)  float4
    const float*  __restrict__ w,      // (32,16)
    float4* __restrict__ out)          // out1 vecs then out2 vecs
{
    const int blk = blockIdx.x;        // 0..1023
    const int ph  = blk & 1;           // pixel half
    const int oc  = (blk >> 1) & 3;    // o-chunk (8 o each)
    const int i   = (blk >> 3) & 15;   // in-plane
    const int b   = blk >> 7;          // batch
    const int p   = ph * 128 + threadIdx.x;  // pixel-vec 0..255

    __shared__ float ws[OUT_P * IN_P];
    #pragma unroll
    for (int k = 0; k < 4; k++)
        ws[threadIdx.x + k * 128] = w[threadIdx.x + k * 128];
    __syncthreads();

    // Load the 16 rep-channels for this (b,i) pixel-vec; keep in registers.
    const float4* xc = x + ((size_t)b * C_X + (size_t)i * REP_C) * PV + p;
    float4 xr[REP_C];
    #pragma unroll
    for (int r = 0; r < REP_C; r++)
        xr[r] = __ldg(&xc[(size_t)r * PV]);

    // Phase 1: gate bits for all 8 o values (4 regs of mask, xr stays live).
    uint m_x = 0u, m_y = 0u, m_z = 0u, m_w = 0u;
    #pragma unroll
    for (int oo = 0; oo < O_PER_C; oo++) {
        const float wv = ws[(oc * O_PER_C + oo) * IN_P + i];
        float tx = 0.f, ty = 0.f, tz = 0.f, tw = 0.f;
        #pragma unroll
        for (int r = 0; r < REP_C; r++) {
            tx += wv * xr[r].x;
            ty += wv * xr[r].y;
            tz += wv * xr[r].z;
            tw += wv * xr[r].w;
        }
        m_x |= (tx > 0.f ? 1u : 0u) << oo;
        m_y |= (ty > 0.f ? 1u : 0u) << oo;
        m_z |= (tz > 0.f ? 1u : 0u) << oo;
        m_w |= (tw > 0.f ? 1u : 0u) << oo;
    }

    // Phase 2: fused streaming-store sweep, 8 o x 16 r.
    float4* ob = out + ((size_t)b * C_OUT1 + (size_t)i * REP_C) * PV + p;
    #pragma unroll
    for (int oo = 0; oo < O_PER_C; oo++) {
        const int o = oc * O_PER_C + oo;
        const float wv = ws[o * IN_P + i];
        const float gx = ((m_x >> oo) & 1u) ? wv : 0.f;
        const float gy = ((m_y >> oo) & 1u) ? wv : 0.f;
        const float gz = ((m_z >> oo) & 1u) ? wv : 0.f;
        const float gw = ((m_w >> oo) & 1u) ? wv : 0.f;

        float4* dst = ob + (size_t)o * (C_X * PV);
        #pragma unroll
        for (int r = 0; r < REP_C; r++) {
            float4 s;
            s.x = gx * xr[r].x;
            s.y = gy * xr[r].y;
            s.z = gz * xr[r].z;
            s.w = gw * xr[r].w;
            __stcs(&dst[(size_t)r * PV], s);   // streaming: never re-read
        }
    }

    // Dense 1x1 conv + ReLU path (tiny): i==0 blocks do their 8 o values.
    if (i == 0) {
        const float4* x2b = x2 + (size_t)b * IN_P * PV + p;
        float ax[O_PER_C], ay[O_PER_C], az[O_PER_C], aw[O_PER_C];
        #pragma unroll
        for (int oo = 0; oo < O_PER_C; oo++)
            ax[oo] = ay[oo] = az[oo] = aw[oo] = 0.f;

        #pragma unroll
        for (int ii = 0; ii < IN_P; ii++) {   // sequential ii: matches einsum
            const float4 v = __ldg(&x2b[(size_t)ii * PV]);
            #pragma unroll
            for (int oo = 0; oo < O_PER_C; oo++) {
                const float wv = ws[(oc * O_PER_C + oo) * IN_P + ii];
                ax[oo] = fmaf(wv, v.x, ax[oo]);
                ay[oo] = fmaf(wv, v.y, ay[oo]);
                az[oo] = fmaf(wv, v.z, az[oo]);
                aw[oo] = fmaf(wv, v.w, aw[oo]);
            }
        }
        #pragma unroll
        for (int oo = 0; oo < O_PER_C; oo++) {
            float4 r;
            r.x = fmaxf(ax[oo], 0.f);
            r.y = fmaxf(ay[oo], 0.f);
            r.z = fmaxf(az[oo], 0.f);
            r.w = fmaxf(aw[oo], 0.f);
            out[OUT1_VECS + ((size_t)b * OUT_P + oc * O_PER_C + oo) * PV + p] = r;
        }
    }
}

extern "C" void kernel_launch(void* const* d_in, const int* in_sizes, int n_in,
                              void* d_out, int out_size)
{
    const float4* x  = (const float4*)d_in[0];
    const float4* x2 = (const float4*)d_in[1];
    const float*  w  = (const float*) d_in[2];
    float4* out = (float4*)d_out;

    qconv_pw_kernel<<<BATCH * IN_P * 4 * 2, 128>>>(x, x2, w, out);
}